// round 7
// baseline (speedup 1.0000x reference)
#include <cuda_runtime.h>
#include <cuda_bf16.h>

// Problem constants (fixed by setup_inputs)
#define BATCH 4
#define CCH 256
#define HH 160
#define WW 160
#define NV 10
#define NH 10
#define NPB 100
#define NP 400
#define KDIM 256
#define HID 256
#define ENCD 128
#define LNEPS 1e-5f

__device__ float g_x[2 * NP * KDIM];   // conv+relu output, patch-flattened
__device__ float g_e[2 * NP * ENCD];   // layernormed embeddings

// packed fp32x2 helpers (Blackwell packed-FP32 pipe; ptxas never auto-emits)
union F4U { float4 f; unsigned long long u[2]; };

__device__ __forceinline__ void ffma2(unsigned long long& d,
                                      unsigned long long a,
                                      unsigned long long b) {
    asm("fma.rn.f32x2 %0, %1, %2, %0;" : "+l"(d) : "l"(a), "l"(b));
}
__device__ __forceinline__ float f2sum(unsigned long long v) {
    float lo, hi;
    asm("mov.b64 {%0, %1}, %2;" : "=f"(lo), "=f"(hi) : "l"(v));
    return lo + hi;
}

// ---------------------------------------------------------------------------
// Kernel 1: 1x1 conv (channel reduction) + bias + relu, patch-flattened write.
// 800 blocks x 256 threads, single wave. __ldcs: single-use stream, evict-first.
// ---------------------------------------------------------------------------
__global__ __launch_bounds__(256) void conv_kernel(
    const float* __restrict__ f1, const float* __restrict__ f2,
    const float* __restrict__ wi, const float* __restrict__ bi,
    const float* __restrict__ wd, const float* __restrict__ bd)
{
    int tid = threadIdx.x;
    int pix = tid & 63;
    int kq  = tid >> 6;                    // 0..3, channels [kq*64, kq*64+64)
    int gid = blockIdx.x * 64 + pix;       // 0..51199
    int t  = gid / 25600;                  // branch (uniform per block)
    int r  = gid % 25600;
    int b  = r / 6400;
    int r2 = r % 6400;
    int y  = r2 / 40;
    int x4 = r2 % 40;

    const float* feat = (t == 0) ? f1 : f2;
    const float* w    = (t == 0) ? wi : wd;
    float bias        = (t == 0) ? bi[0] : bd[0];

    __shared__ float ws[CCH];
    __shared__ float4 part[256];
    if (tid < 256) ws[tid] = w[tid];
    __syncthreads();

    const float4* fp = (const float4*)feat
                     + (size_t)b * CCH * 6400 + (size_t)kq * 64 * 6400
                     + y * 40 + x4;
    float4 acc = make_float4(0.f, 0.f, 0.f, 0.f);
    #pragma unroll 4
    for (int c = 0; c < 64; c++) {
        float4 v = __ldcs(fp + c * 6400);
        float wc = ws[kq * 64 + c];
        acc.x = fmaf(wc, v.x, acc.x);
        acc.y = fmaf(wc, v.y, acc.y);
        acc.z = fmaf(wc, v.z, acc.z);
        acc.w = fmaf(wc, v.w, acc.w);
    }
    part[kq * 64 + pix] = acc;
    __syncthreads();

    if (tid < 64) {
        float4 a0 = part[tid];
        float4 a1 = part[64 + tid];
        float4 a2 = part[128 + tid];
        float4 a3 = part[192 + tid];
        float4 o;
        o.x = fmaxf(a0.x + a1.x + a2.x + a3.x + bias, 0.f);
        o.y = fmaxf(a0.y + a1.y + a2.y + a3.y + bias, 0.f);
        o.z = fmaxf(a0.z + a1.z + a2.z + a3.z + bias, 0.f);
        o.w = fmaxf(a0.w + a1.w + a2.w + a3.w + bias, 0.f);

        int gid0 = blockIdx.x * 64 + tid;
        int t0  = gid0 / 25600;
        int r0  = gid0 % 25600;
        int b0  = r0 / 6400;
        int r20 = r0 % 6400;
        int y0  = r20 / 40;
        int x40 = r20 % 40;
        int v_ = y0 >> 4, ii = y0 & 15;
        int h_ = x40 >> 2, j0 = (x40 & 3) * 4;
        int patch = b0 * NPB + v_ * NH + h_;
        int idx = (t0 * NP + patch) * KDIM + ii * 16 + j0;
        *(float4*)(g_x + idx) = o;
    }
}

// ---------------------------------------------------------------------------
// Kernel 2: per-patch MLP (256 -> relu 256 -> 128) + LayerNorm.
// 200 blocks x 512 threads, 4 patches/block, packed f32x2 FMA over k-pairs.
// GEMM1: 128 o-groups(2 rows) x 4 k-splits(64).  GEMM2: 64 og(2) x 8 ks(32).
// ---------------------------------------------------------------------------
__global__ __launch_bounds__(512) void mlp_kernel(
    const float* __restrict__ w1i, const float* __restrict__ w2i,
    const float* __restrict__ gi,  const float* __restrict__ bi,
    const float* __restrict__ w1d, const float* __restrict__ w2d,
    const float* __restrict__ gd,  const float* __restrict__ bd)
{
    int bid = blockIdx.x;          // 0..199
    int t   = bid / 100;
    int pg  = bid % 100;
    int p0  = pg * 4;              // 4 patches per block

    const float* W1 = t ? w1d : w1i;
    const float* W2 = t ? w2d : w2i;
    const float* LG = t ? gd : gi;
    const float* LB = t ? bd : bi;

    __shared__ float xs[4 * HID];      // x tile, reused as h tile [p][k]
    __shared__ float part[4096];       // [4][4][256] then [8][4][128]
    __shared__ float es[4 * ENCD];     // embeddings [p][d]

    int tid = threadIdx.x;

    // load 4 x-vectors (4*256 floats = 256 float4)
    if (tid < 256) {
        const float4* xg = (const float4*)(g_x + (size_t)(t * NP + p0) * KDIM);
        ((float4*)xs)[tid] = xg[tid];
    }
    __syncthreads();

    // ---- GEMM1: h = relu(W1 @ x) ----
    {
        int og = tid & 127, kq = tid >> 7;     // 128 o-groups x 4 k-splits
        int o0 = og * 2, k0 = kq * 64;
        unsigned long long acc2[2][4];
        #pragma unroll
        for (int i = 0; i < 2; i++)
            #pragma unroll
            for (int p = 0; p < 4; p++) acc2[i][p] = 0ull;

        for (int kk = 0; kk < 64; kk += 4) {
            int k = k0 + kk;
            F4U xv[4];
            #pragma unroll
            for (int p = 0; p < 4; p++) xv[p].f = *(const float4*)(xs + p * HID + k);
            #pragma unroll
            for (int i = 0; i < 2; i++) {
                F4U wv; wv.f = *(const float4*)(W1 + (o0 + i) * HID + k);
                #pragma unroll
                for (int p = 0; p < 4; p++) {
                    ffma2(acc2[i][p], wv.u[0], xv[p].u[0]);
                    ffma2(acc2[i][p], wv.u[1], xv[p].u[1]);
                }
            }
        }
        #pragma unroll
        for (int p = 0; p < 4; p++) {
            float2 v = make_float2(f2sum(acc2[0][p]), f2sum(acc2[1][p]));
            *(float2*)(part + kq * 1024 + p * 256 + o0) = v;
        }
    }
    __syncthreads();

    // reduce 4 k-splits, relu, write h into xs[p][o]  (512 threads: 2 halves)
    {
        int o = tid & 255, ph = tid >> 8;      // ph = 0/1 -> patches 0-1 / 2-3
        #pragma unroll
        for (int pi = 0; pi < 2; pi++) {
            int p = ph * 2 + pi;
            float s = part[           p * 256 + o]
                    + part[1 * 1024 + p * 256 + o]
                    + part[2 * 1024 + p * 256 + o]
                    + part[3 * 1024 + p * 256 + o];
            xs[p * HID + o] = fmaxf(s, 0.f);
        }
    }
    __syncthreads();

    // ---- GEMM2: e = W2 @ h ----
    {
        int og = tid & 63, kq = tid >> 6;      // 64 o-groups x 8 k-splits
        int o0 = og * 2, k0 = kq * 32;
        unsigned long long acc2[2][4];
        #pragma unroll
        for (int i = 0; i < 2; i++)
            #pragma unroll
            for (int p = 0; p < 4; p++) acc2[i][p] = 0ull;

        for (int kk = 0; kk < 32; kk += 4) {
            int k = k0 + kk;
            F4U xv[4];
            #pragma unroll
            for (int p = 0; p < 4; p++) xv[p].f = *(const float4*)(xs + p * HID + k);
            #pragma unroll
            for (int i = 0; i < 2; i++) {
                F4U wv; wv.f = *(const float4*)(W2 + (o0 + i) * HID + k);
                #pragma unroll
                for (int p = 0; p < 4; p++) {
                    ffma2(acc2[i][p], wv.u[0], xv[p].u[0]);
                    ffma2(acc2[i][p], wv.u[1], xv[p].u[1]);
                }
            }
        }
        #pragma unroll
        for (int p = 0; p < 4; p++) {
            float2 v = make_float2(f2sum(acc2[0][p]), f2sum(acc2[1][p]));
            *(float2*)(part + kq * 512 + p * 128 + o0) = v;
        }
    }
    __syncthreads();

    // reduce 8 k-splits -> es[p][d]  (512 threads: 4 quarters, 1 patch each)
    {
        int d = tid & 127, pq = tid >> 7;      // pq = 0..3 -> patch pq
        float s = 0.f;
        #pragma unroll
        for (int q = 0; q < 8; q++) s += part[q * 512 + pq * 128 + d];
        es[pq * ENCD + d] = s;
    }
    __syncthreads();

    // ---- LayerNorm: warps 0..3 handle patches 0..3 ----
    int warp = tid >> 5, lane = tid & 31;
    if (warp < 4) {
        float4 v = *(const float4*)(es + warp * ENCD + lane * 4);
        float s  = v.x + v.y + v.z + v.w;
        float sq = v.x * v.x + v.y * v.y + v.z * v.z + v.w * v.w;
        #pragma unroll
        for (int off = 16; off > 0; off >>= 1) {
            s  += __shfl_xor_sync(0xffffffffu, s,  off);
            sq += __shfl_xor_sync(0xffffffffu, sq, off);
        }
        float mu   = s * (1.f / ENCD);
        float var  = sq * (1.f / ENCD) - mu * mu;
        float rstd = rsqrtf(var + LNEPS);
        float4 g4  = *(const float4*)(LG + lane * 4);
        float4 b4  = *(const float4*)(LB + lane * 4);
        float4 o;
        o.x = (v.x - mu) * rstd * g4.x + b4.x;
        o.y = (v.y - mu) * rstd * g4.y + b4.y;
        o.z = (v.z - mu) * rstd * g4.z + b4.z;
        o.w = (v.w - mu) * rstd * g4.w + b4.w;
        *(float4*)(g_e + (size_t)(t * NP + p0 + warp) * ENCD + lane * 4) = o;
    }
}

// ---------------------------------------------------------------------------
// Kernel 3: logits[b,n,m] = scale * dot(e1[b,n], e2[b,m]) + transpose write.
// 64 blocks (4 batches x 4x4 chunks of 25x25) x 128 threads.
// 100 threads = 25 (5x5 reg tile) x 4 k-splits of 32; f32x2 FMA; smem reduce.
// ---------------------------------------------------------------------------
__global__ __launch_bounds__(128) void logits_kernel(
    const float* __restrict__ lsc, float* __restrict__ out)
{
    int b   = blockIdx.x >> 4;
    int nch = (blockIdx.x >> 2) & 3;
    int mch = blockIdx.x & 3;
    int n0 = nch * 25, m0 = mch * 25;

    __shared__ float e1s[25 * 132];   // 25 rows x 128 k, pitch 33 float4
    __shared__ float e2s[25 * 132];
    __shared__ float part[4 * 625];

    int tid = threadIdx.x;
    float scale = expf(lsc[0]);

    const float4* e1g = (const float4*)(g_e + (size_t)(b * NPB + n0) * ENCD);
    const float4* e2g = (const float4*)(g_e + (size_t)NP * ENCD + (size_t)(b * NPB + m0) * ENCD);

    for (int i = tid; i < 25 * 32; i += 128) {
        int r = i >> 5, c = i & 31;
        ((float4*)e1s)[r * 33 + c] = e1g[r * 32 + c];
        ((float4*)e2s)[r * 33 + c] = e2g[r * 32 + c];
    }
    __syncthreads();

    if (tid < 100) {
        int kq = tid / 25;          // k-split 0..3 (8 float4 each)
        int tt = tid % 25;
        int tn = tt / 5, tm = tt % 5;
        int c0 = kq * 8;

        unsigned long long acc2[5][5];
        #pragma unroll
        for (int i = 0; i < 5; i++)
            #pragma unroll
            for (int j = 0; j < 5; j++) acc2[i][j] = 0ull;

        #pragma unroll
        for (int c = 0; c < 8; c++) {
            F4U a[5], bb[5];
            #pragma unroll
            for (int i = 0; i < 5; i++) a[i].f  = ((float4*)e1s)[(tn * 5 + i) * 33 + c0 + c];
            #pragma unroll
            for (int j = 0; j < 5; j++) bb[j].f = ((float4*)e2s)[(tm * 5 + j) * 33 + c0 + c];
            #pragma unroll
            for (int i = 0; i < 5; i++)
                #pragma unroll
                for (int j = 0; j < 5; j++) {
                    ffma2(acc2[i][j], a[i].u[0], bb[j].u[0]);
                    ffma2(acc2[i][j], a[i].u[1], bb[j].u[1]);
                }
        }
        #pragma unroll
        for (int i = 0; i < 5; i++)
            #pragma unroll
            for (int j = 0; j < 5; j++)
                part[kq * 625 + (tn * 5 + i) * 25 + (tm * 5 + j)] = f2sum(acc2[i][j]);
    }
    __syncthreads();

    if (tid < 125) {
        #pragma unroll
        for (int u = 0; u < 5; u++) {
            int o = tid * 5 + u;               // 0..624
            int ni = o / 25, mi = o % 25;
            float s = part[o] + part[625 + o] + part[1250 + o] + part[1875 + o];
            float val = scale * s;
            int n = n0 + ni, m = m0 + mi;
            out[(b * NPB + n) * NPB + m] = val;
            out[40000 + (b * NPB + m) * NPB + n] = val;
        }
    }
}

// ---------------------------------------------------------------------------
extern "C" void kernel_launch(void* const* d_in, const int* in_sizes, int n_in,
                              void* d_out, int out_size)
{
    const float* feat_c1      = (const float*)d_in[0];
    const float* feat_c2      = (const float*)d_in[1];
    const float* img_conv_w   = (const float*)d_in[3];
    const float* img_conv_b   = (const float*)d_in[4];
    const float* img_w1       = (const float*)d_in[5];
    const float* img_w2       = (const float*)d_in[6];
    const float* img_ln_g     = (const float*)d_in[7];
    const float* img_ln_b     = (const float*)d_in[8];
    const float* depth_conv_w = (const float*)d_in[9];
    const float* depth_conv_b = (const float*)d_in[10];
    const float* depth_w1     = (const float*)d_in[11];
    const float* depth_w2     = (const float*)d_in[12];
    const float* depth_ln_g   = (const float*)d_in[13];
    const float* depth_ln_b   = (const float*)d_in[14];
    const float* logit_scale  = (const float*)d_in[15];
    float* out = (float*)d_out;

    conv_kernel<<<800, 256>>>(feat_c1, feat_c2, img_conv_w, img_conv_b,
                              depth_conv_w, depth_conv_b);
    mlp_kernel<<<200, 512>>>(img_w1, img_w2, img_ln_g, img_ln_b,
                             depth_w1, depth_w2, depth_ln_g, depth_ln_b);
    logits_kernel<<<64, 128>>>(logit_scale, out);
}

// round 10
// speedup vs baseline: 1.3176x; 1.3176x over previous
#include <cuda_runtime.h>
#include <cuda_bf16.h>

// Problem constants (fixed by setup_inputs)
#define BATCH 4
#define CCH 256
#define HH 160
#define WW 160
#define NV 10
#define NH 10
#define NPB 100
#define NP 400
#define KDIM 256
#define HID 256
#define ENCD 128
#define LNEPS 1e-5f

__device__ float g_x[2 * NP * KDIM];   // conv+relu output, patch-flattened
__device__ float g_e[2 * NP * ENCD];   // layernormed embeddings

// packed fp32x2 helpers (Blackwell packed-FP32 pipe; ptxas never auto-emits)
union F4U { float4 f; unsigned long long u[2]; };

__device__ __forceinline__ void ffma2(unsigned long long& d,
                                      unsigned long long a,
                                      unsigned long long b) {
    asm("fma.rn.f32x2 %0, %1, %2, %0;" : "+l"(d) : "l"(a), "l"(b));
}
__device__ __forceinline__ float f2sum(unsigned long long v) {
    float lo, hi;
    asm("mov.b64 {%0, %1}, %2;" : "=f"(lo), "=f"(hi) : "l"(v));
    return lo + hi;
}

// ---------------------------------------------------------------------------
// Kernel 1: 1x1 conv (channel reduction) + bias + relu, patch-flattened write.
// 800 blocks x 256 threads, single wave. __ldcs: single-use stream.
// ---------------------------------------------------------------------------
__global__ __launch_bounds__(256) void conv_kernel(
    const float* __restrict__ f1, const float* __restrict__ f2,
    const float* __restrict__ wi, const float* __restrict__ bi,
    const float* __restrict__ wd, const float* __restrict__ bd)
{
    int tid = threadIdx.x;
    int pix = tid & 63;
    int kq  = tid >> 6;                    // 0..3, channels [kq*64, kq*64+64)
    int gid = blockIdx.x * 64 + pix;       // 0..51199
    int t  = gid / 25600;                  // branch (uniform per block)
    int r  = gid % 25600;
    int b  = r / 6400;
    int r2 = r % 6400;
    int y  = r2 / 40;
    int x4 = r2 % 40;

    const float* feat = (t == 0) ? f1 : f2;
    const float* w    = (t == 0) ? wi : wd;
    float bias        = (t == 0) ? bi[0] : bd[0];

    __shared__ float ws[CCH];
    __shared__ float4 part[256];
    if (tid < 256) ws[tid] = w[tid];
    __syncthreads();

    const float4* fp = (const float4*)feat
                     + (size_t)b * CCH * 6400 + (size_t)kq * 64 * 6400
                     + y * 40 + x4;
    float4 acc = make_float4(0.f, 0.f, 0.f, 0.f);
    #pragma unroll 4
    for (int c = 0; c < 64; c++) {
        float4 v = __ldcs(fp + c * 6400);
        float wc = ws[kq * 64 + c];
        acc.x = fmaf(wc, v.x, acc.x);
        acc.y = fmaf(wc, v.y, acc.y);
        acc.z = fmaf(wc, v.z, acc.z);
        acc.w = fmaf(wc, v.w, acc.w);
    }
    part[kq * 64 + pix] = acc;
    __syncthreads();

    if (tid < 64) {
        float4 a0 = part[tid];
        float4 a1 = part[64 + tid];
        float4 a2 = part[128 + tid];
        float4 a3 = part[192 + tid];
        float4 o;
        o.x = fmaxf(a0.x + a1.x + a2.x + a3.x + bias, 0.f);
        o.y = fmaxf(a0.y + a1.y + a2.y + a3.y + bias, 0.f);
        o.z = fmaxf(a0.z + a1.z + a2.z + a3.z + bias, 0.f);
        o.w = fmaxf(a0.w + a1.w + a2.w + a3.w + bias, 0.f);

        int gid0 = blockIdx.x * 64 + tid;
        int t0  = gid0 / 25600;
        int r0  = gid0 % 25600;
        int b0  = r0 / 6400;
        int r20 = r0 % 6400;
        int y0  = r20 / 40;
        int x40 = r20 % 40;
        int v_ = y0 >> 4, ii = y0 & 15;
        int h_ = x40 >> 2, j0 = (x40 & 3) * 4;
        int patch = b0 * NPB + v_ * NH + h_;
        int idx = (t0 * NP + patch) * KDIM + ii * 16 + j0;
        *(float4*)(g_x + idx) = o;
    }
}

// ---------------------------------------------------------------------------
// Kernel 2: per-patch MLP (256 -> relu 256 -> 128) + LayerNorm.
// 100 blocks x 512 threads, 8 patches/block, single-pass weights (38MB L2).
// Lane layout: rgrp=lane>>3 (4 rows), ksub=lane&7 (16B k-chunk) -> every warp
// LDG.128 covers 4 rows x 128B contiguous = 4 L1 lines (8x fewer wavefronts
// than the o-strided layout). Per-lane k-slice partials reduced via shfl_xor.
// f32x2 packed FMA throughout.
// ---------------------------------------------------------------------------
__global__ __launch_bounds__(512) void mlp_kernel(
    const float* __restrict__ w1i, const float* __restrict__ w2i,
    const float* __restrict__ gi,  const float* __restrict__ bi,
    const float* __restrict__ w1d, const float* __restrict__ w2d,
    const float* __restrict__ gd,  const float* __restrict__ bd)
{
    int bid = blockIdx.x;          // 0..99
    int t   = bid / 50;
    int pg  = bid % 50;
    int p0  = pg * 8;              // 8 patches per block

    const float* W1 = t ? w1d : w1i;
    const float* W2 = t ? w2d : w2i;
    const float* LG = t ? gd : gi;
    const float* LB = t ? bd : bi;

    __shared__ float xs[8 * HID];      // x vectors [p][k]
    __shared__ float hs[8 * HID];      // hidden    [p][o]
    __shared__ float es[8 * ENCD];     // embeddings [p][d]

    int tid = threadIdx.x;

    // load 8 x-vectors (8*256 floats = 512 float4)
    {
        const float4* xg = (const float4*)(g_x + (size_t)(t * NP + p0) * KDIM);
        ((float4*)xs)[tid] = xg[tid];
    }
    __syncthreads();

    int warp = tid >> 5, lane = tid & 31;
    int rgrp = lane >> 3, ksub = lane & 7;
    int koff = ksub * 4;

    // ---- GEMM1: h = relu(W1 @ x), 256 rows, 16 rows/warp ----
    #pragma unroll
    for (int pass = 0; pass < 2; pass++) {
        unsigned long long acc2[2][8];
        #pragma unroll
        for (int it = 0; it < 2; it++)
            #pragma unroll
            for (int p = 0; p < 8; p++) acc2[it][p] = 0ull;

        #pragma unroll 2
        for (int kc = 0; kc < 8; kc++) {
            int k = kc * 32 + koff;
            F4U xv[8];
            #pragma unroll
            for (int p = 0; p < 8; p++) xv[p].f = *(const float4*)(xs + p * HID + k);
            #pragma unroll
            for (int it = 0; it < 2; it++) {
                int r = warp * 16 + pass * 8 + it * 4 + rgrp;
                F4U wv; wv.f = *(const float4*)(W1 + r * HID + k);
                #pragma unroll
                for (int p = 0; p < 8; p++) {
                    ffma2(acc2[it][p], wv.u[0], xv[p].u[0]);
                    ffma2(acc2[it][p], wv.u[1], xv[p].u[1]);
                }
            }
        }
        #pragma unroll
        for (int it = 0; it < 2; it++) {
            int r = warp * 16 + pass * 8 + it * 4 + rgrp;
            #pragma unroll
            for (int p = 0; p < 8; p++) {
                float s = f2sum(acc2[it][p]);
                s += __shfl_xor_sync(0xffffffffu, s, 1);
                s += __shfl_xor_sync(0xffffffffu, s, 2);
                s += __shfl_xor_sync(0xffffffffu, s, 4);
                if (ksub == 0) hs[p * HID + r] = fmaxf(s, 0.f);
            }
        }
    }
    __syncthreads();

    // ---- GEMM2: e = W2 @ h, 128 rows, 8 rows/warp ----
    {
        unsigned long long acc2[2][8];
        #pragma unroll
        for (int it = 0; it < 2; it++)
            #pragma unroll
            for (int p = 0; p < 8; p++) acc2[it][p] = 0ull;

        #pragma unroll 2
        for (int kc = 0; kc < 8; kc++) {
            int k = kc * 32 + koff;
            F4U xv[8];
            #pragma unroll
            for (int p = 0; p < 8; p++) xv[p].f = *(const float4*)(hs + p * HID + k);
            #pragma unroll
            for (int it = 0; it < 2; it++) {
                int r = warp * 8 + it * 4 + rgrp;
                F4U wv; wv.f = *(const float4*)(W2 + r * HID + k);
                #pragma unroll
                for (int p = 0; p < 8; p++) {
                    ffma2(acc2[it][p], wv.u[0], xv[p].u[0]);
                    ffma2(acc2[it][p], wv.u[1], xv[p].u[1]);
                }
            }
        }
        #pragma unroll
        for (int it = 0; it < 2; it++) {
            int r = warp * 8 + it * 4 + rgrp;
            #pragma unroll
            for (int p = 0; p < 8; p++) {
                float s = f2sum(acc2[it][p]);
                s += __shfl_xor_sync(0xffffffffu, s, 1);
                s += __shfl_xor_sync(0xffffffffu, s, 2);
                s += __shfl_xor_sync(0xffffffffu, s, 4);
                if (ksub == 0) es[p * ENCD + r] = s;
            }
        }
    }
    __syncthreads();

    // ---- LayerNorm: warps 0..7 handle patches 0..7 ----
    if (warp < 8) {
        float4 v = *(const float4*)(es + warp * ENCD + lane * 4);
        float s  = v.x + v.y + v.z + v.w;
        float sq = v.x * v.x + v.y * v.y + v.z * v.z + v.w * v.w;
        #pragma unroll
        for (int off = 16; off > 0; off >>= 1) {
            s  += __shfl_xor_sync(0xffffffffu, s,  off);
            sq += __shfl_xor_sync(0xffffffffu, sq, off);
        }
        float mu   = s * (1.f / ENCD);
        float var  = sq * (1.f / ENCD) - mu * mu;
        float rstd = rsqrtf(var + LNEPS);
        float4 g4  = *(const float4*)(LG + lane * 4);
        float4 b4  = *(const float4*)(LB + lane * 4);
        float4 o;
        o.x = (v.x - mu) * rstd * g4.x + b4.x;
        o.y = (v.y - mu) * rstd * g4.y + b4.y;
        o.z = (v.z - mu) * rstd * g4.z + b4.z;
        o.w = (v.w - mu) * rstd * g4.w + b4.w;
        *(float4*)(g_e + (size_t)(t * NP + p0 + warp) * ENCD + lane * 4) = o;
    }
}

// ---------------------------------------------------------------------------
// Kernel 3: logits[b,n,m] = scale * dot(e1[b,n], e2[b,m]) + transpose write.
// 64 blocks (4 batches x 4x4 chunks of 25x25) x 128 threads.
// 100 threads = 25 (5x5 reg tile) x 4 k-splits of 32; f32x2 FMA; smem reduce.
// ---------------------------------------------------------------------------
__global__ __launch_bounds__(128) void logits_kernel(
    const float* __restrict__ lsc, float* __restrict__ out)
{
    int b   = blockIdx.x >> 4;
    int nch = (blockIdx.x >> 2) & 3;
    int mch = blockIdx.x & 3;
    int n0 = nch * 25, m0 = mch * 25;

    __shared__ float e1s[25 * 132];   // 25 rows x 128 k, pitch 33 float4
    __shared__ float e2s[25 * 132];
    __shared__ float part[4 * 625];

    int tid = threadIdx.x;
    float scale = expf(lsc[0]);

    const float4* e1g = (const float4*)(g_e + (size_t)(b * NPB + n0) * ENCD);
    const float4* e2g = (const float4*)(g_e + (size_t)NP * ENCD + (size_t)(b * NPB + m0) * ENCD);

    for (int i = tid; i < 25 * 32; i += 128) {
        int r = i >> 5, c = i & 31;
        ((float4*)e1s)[r * 33 + c] = e1g[r * 32 + c];
        ((float4*)e2s)[r * 33 + c] = e2g[r * 32 + c];
    }
    __syncthreads();

    if (tid < 100) {
        int kq = tid / 25;          // k-split 0..3 (8 float4 each)
        int tt = tid % 25;
        int tn = tt / 5, tm = tt % 5;
        int c0 = kq * 8;

        unsigned long long acc2[5][5];
        #pragma unroll
        for (int i = 0; i < 5; i++)
            #pragma unroll
            for (int j = 0; j < 5; j++) acc2[i][j] = 0ull;

        #pragma unroll
        for (int c = 0; c < 8; c++) {
            F4U a[5], bb[5];
            #pragma unroll
            for (int i = 0; i < 5; i++) a[i].f  = ((float4*)e1s)[(tn * 5 + i) * 33 + c0 + c];
            #pragma unroll
            for (int j = 0; j < 5; j++) bb[j].f = ((float4*)e2s)[(tm * 5 + j) * 33 + c0 + c];
            #pragma unroll
            for (int i = 0; i < 5; i++)
                #pragma unroll
                for (int j = 0; j < 5; j++) {
                    ffma2(acc2[i][j], a[i].u[0], bb[j].u[0]);
                    ffma2(acc2[i][j], a[i].u[1], bb[j].u[1]);
                }
        }
        #pragma unroll
        for (int i = 0; i < 5; i++)
            #pragma unroll
            for (int j = 0; j < 5; j++)
                part[kq * 625 + (tn * 5 + i) * 25 + (tm * 5 + j)] = f2sum(acc2[i][j]);
    }
    __syncthreads();

    if (tid < 125) {
        #pragma unroll
        for (int u = 0; u < 5; u++) {
            int o = tid * 5 + u;               // 0..624
            int ni = o / 25, mi = o % 25;
            float s = part[o] + part[625 + o] + part[1250 + o] + part[1875 + o];
            float val = scale * s;
            int n = n0 + ni, m = m0 + mi;
            out[(b * NPB + n) * NPB + m] = val;
            out[40000 + (b * NPB + m) * NPB + n] = val;
        }
    }
}

// ---------------------------------------------------------------------------
extern "C" void kernel_launch(void* const* d_in, const int* in_sizes, int n_in,
                              void* d_out, int out_size)
{
    const float* feat_c1      = (const float*)d_in[0];
    const float* feat_c2      = (const float*)d_in[1];
    const float* img_conv_w   = (const float*)d_in[3];
    const float* img_conv_b   = (const float*)d_in[4];
    const float* img_w1       = (const float*)d_in[5];
    const float* img_w2       = (const float*)d_in[6];
    const float* img_ln_g     = (const float*)d_in[7];
    const float* img_ln_b     = (const float*)d_in[8];
    const float* depth_conv_w = (const float*)d_in[9];
    const float* depth_conv_b = (const float*)d_in[10];
    const float* depth_w1     = (const float*)d_in[11];
    const float* depth_w2     = (const float*)d_in[12];
    const float* depth_ln_g   = (const float*)d_in[13];
    const float* depth_ln_b   = (const float*)d_in[14];
    const float* logit_scale  = (const float*)d_in[15];
    float* out = (float*)d_out;

    conv_kernel<<<800, 256>>>(feat_c1, feat_c2, img_conv_w, img_conv_b,
                              depth_conv_w, depth_conv_b);
    mlp_kernel<<<100, 512>>>(img_w1, img_w2, img_ln_g, img_ln_b,
                             depth_w1, depth_w2, depth_ln_g, depth_ln_b);
    logits_kernel<<<64, 128>>>(logit_scale, out);
}

// round 15
// speedup vs baseline: 1.3641x; 1.0353x over previous
#include <cuda_runtime.h>
#include <cuda_bf16.h>

// Problem constants (fixed by setup_inputs)
#define CCH 256
#define NPB 100
#define NHG 10            // grid cols (nh)
#define NP 400
#define NPAD 456          // per-branch padded patch count (152 blocks x 6)
#define KDIM 256
#define HID 256
#define ENCD 128
#define LNEPS 1e-5f
#define GRIDSZ 152
#define BPB 76            // blocks per branch
#define PPB 6             // patches per block

__device__ float g_x[2 * NPAD * KDIM];   // conv+relu out; pad region stays 0 (.bss)
__device__ float g_e[2 * NPAD * ENCD];   // layernormed embeddings
__device__ unsigned g_bar = 0;           // self-resetting grid barrier counter

// packed fp32x2 helpers (ptxas never auto-emits FFMA2)
union F4U { float4 f; unsigned long long u[2]; };

__device__ __forceinline__ void ffma2(unsigned long long& d,
                                      unsigned long long a,
                                      unsigned long long b) {
    asm("fma.rn.f32x2 %0, %1, %2, %0;" : "+l"(d) : "l"(a), "l"(b));
}
__device__ __forceinline__ float f2sum(unsigned long long v) {
    float lo, hi;
    asm("mov.b64 {%0, %1}, %2;" : "=f"(lo), "=f"(hi) : "l"(v));
    return lo + hi;
}

// ---------------------------------------------------------------------------
// Kernel 1: 1x1 conv (channel reduction) + bias + relu, patch-flattened write.
// 800 blocks x 256 threads, single wave, HBM-bound (~6.2 TB/s = near ceiling).
// ---------------------------------------------------------------------------
__global__ __launch_bounds__(256) void conv_kernel(
    const float* __restrict__ f1, const float* __restrict__ f2,
    const float* __restrict__ wi, const float* __restrict__ bi,
    const float* __restrict__ wd, const float* __restrict__ bd)
{
    int tid = threadIdx.x;
    int pix = tid & 63;
    int kq  = tid >> 6;                    // 0..3, channels [kq*64, kq*64+64)
    int gid = blockIdx.x * 64 + pix;       // 0..51199
    int t  = gid / 25600;                  // branch (uniform per block)
    int r  = gid % 25600;
    int b  = r / 6400;
    int r2 = r % 6400;
    int y  = r2 / 40;
    int x4 = r2 % 40;

    const float* feat = (t == 0) ? f1 : f2;
    const float* w    = (t == 0) ? wi : wd;
    float bias        = (t == 0) ? bi[0] : bd[0];

    __shared__ float ws[CCH];
    __shared__ float4 part[256];
    if (tid < 256) ws[tid] = w[tid];
    __syncthreads();

    const float4* fp = (const float4*)feat
                     + (size_t)b * CCH * 6400 + (size_t)kq * 64 * 6400
                     + y * 40 + x4;
    float4 acc = make_float4(0.f, 0.f, 0.f, 0.f);
    #pragma unroll 4
    for (int c = 0; c < 64; c++) {
        float4 v = __ldcs(fp + c * 6400);
        float wc = ws[kq * 64 + c];
        acc.x = fmaf(wc, v.x, acc.x);
        acc.y = fmaf(wc, v.y, acc.y);
        acc.z = fmaf(wc, v.z, acc.z);
        acc.w = fmaf(wc, v.w, acc.w);
    }
    part[kq * 64 + pix] = acc;
    __syncthreads();

    if (tid < 64) {
        float4 a0 = part[tid];
        float4 a1 = part[64 + tid];
        float4 a2 = part[128 + tid];
        float4 a3 = part[192 + tid];
        float4 o;
        o.x = fmaxf(a0.x + a1.x + a2.x + a3.x + bias, 0.f);
        o.y = fmaxf(a0.y + a1.y + a2.y + a3.y + bias, 0.f);
        o.z = fmaxf(a0.z + a1.z + a2.z + a3.z + bias, 0.f);
        o.w = fmaxf(a0.w + a1.w + a2.w + a3.w + bias, 0.f);

        int gid0 = blockIdx.x * 64 + tid;
        int t0  = gid0 / 25600;
        int r0  = gid0 % 25600;
        int b0  = r0 / 6400;
        int r20 = r0 % 6400;
        int y0  = r20 / 40;
        int x40 = r20 % 40;
        int v_ = y0 >> 4, ii = y0 & 15;
        int h_ = x40 >> 2, j0 = (x40 & 3) * 4;
        int patch = b0 * NPB + v_ * NHG + h_;
        int idx = (t0 * NPAD + patch) * KDIM + ii * 16 + j0;
        *(float4*)(g_x + idx) = o;
    }
}

// ---------------------------------------------------------------------------
// Kernel 2 (fused): MLP (256 -> relu 256 -> 128) + LayerNorm, grid barrier,
// then logits.  152 blocks x 256 threads, 6 patches/block (branch-padded).
// Lane layout: rgrp=lane>>3 (4 rows / LDG line-group), ksub=lane&7 (16B k).
// wv[4] hoisted per k-chunk so each x float4 is LDS'd once per 16-row group.
// Grid barrier: atomicInc wrap-to-0 (self-resetting across graph replays;
// 152 blocks = all-resident single wave -> deadlock-free).
// ---------------------------------------------------------------------------
__global__ __launch_bounds__(256) void mlp_logits_kernel(
    const float* __restrict__ w1i, const float* __restrict__ w2i,
    const float* __restrict__ gi,  const float* __restrict__ bi,
    const float* __restrict__ w1d, const float* __restrict__ w2d,
    const float* __restrict__ gd,  const float* __restrict__ bd,
    const float* __restrict__ lsc, float* __restrict__ out)
{
    __shared__ float S[7936];
    float* xs = S;             // [6][256]  x vectors (phase 1)
    float* hs = S + 1536;      // [6][256]  hidden
    float* es = S + 3072;      // [6][128]  embeddings

    int tid = threadIdx.x;
    int bid = blockIdx.x;
    int t   = bid / BPB;        // branch
    int pg  = bid % BPB;
    int p0  = pg * PPB;         // 0..450 (>=400 are zero-pad patches)

    const float* W1 = t ? w1d : w1i;
    const float* W2 = t ? w2d : w2i;
    const float* LG = t ? gd : gi;
    const float* LB = t ? bd : bi;

    {
        const float4* xg = (const float4*)(g_x + (size_t)(t * NPAD + p0) * KDIM);
        for (int i = tid; i < 384; i += 256) ((float4*)xs)[i] = xg[i];
    }
    __syncthreads();

    int warp = tid >> 5, lane = tid & 31;
    int rgrp = lane >> 3, ksub = lane & 7;
    int koff = ksub * 4;

    // ---- GEMM1: h = relu(W1 @ x), 256 rows = 8 warps x 2 passes x 16 rows ----
    #pragma unroll
    for (int pass = 0; pass < 2; pass++) {
        unsigned long long acc2[4][6];
        #pragma unroll
        for (int it = 0; it < 4; it++)
            #pragma unroll
            for (int p = 0; p < 6; p++) acc2[it][p] = 0ull;

        #pragma unroll 2
        for (int kc = 0; kc < 8; kc++) {
            int k = kc * 32 + koff;
            F4U wv[4];
            #pragma unroll
            for (int it = 0; it < 4; it++) {
                int r = warp * 32 + pass * 16 + it * 4 + rgrp;
                wv[it].f = *(const float4*)(W1 + r * HID + k);
            }
            #pragma unroll
            for (int ph = 0; ph < 2; ph++) {
                F4U xv[3];
                #pragma unroll
                for (int pp = 0; pp < 3; pp++)
                    xv[pp].f = *(const float4*)(xs + (ph * 3 + pp) * HID + k);
                #pragma unroll
                for (int it = 0; it < 4; it++)
                    #pragma unroll
                    for (int pp = 0; pp < 3; pp++) {
                        ffma2(acc2[it][ph * 3 + pp], wv[it].u[0], xv[pp].u[0]);
                        ffma2(acc2[it][ph * 3 + pp], wv[it].u[1], xv[pp].u[1]);
                    }
            }
        }
        #pragma unroll
        for (int it = 0; it < 4; it++) {
            int r = warp * 32 + pass * 16 + it * 4 + rgrp;
            #pragma unroll
            for (int p = 0; p < 6; p++) {
                float s = f2sum(acc2[it][p]);
                s += __shfl_xor_sync(0xffffffffu, s, 1);
                s += __shfl_xor_sync(0xffffffffu, s, 2);
                s += __shfl_xor_sync(0xffffffffu, s, 4);
                if (ksub == 0) hs[p * HID + r] = fmaxf(s, 0.f);
            }
        }
    }
    __syncthreads();

    // ---- GEMM2: e = W2 @ h, 128 rows = 8 warps x 16 rows, one pass ----
    {
        unsigned long long acc2[4][6];
        #pragma unroll
        for (int it = 0; it < 4; it++)
            #pragma unroll
            for (int p = 0; p < 6; p++) acc2[it][p] = 0ull;

        #pragma unroll 2
        for (int kc = 0; kc < 8; kc++) {
            int k = kc * 32 + koff;
            F4U wv[4];
            #pragma unroll
            for (int it = 0; it < 4; it++) {
                int r = warp * 16 + it * 4 + rgrp;
                wv[it].f = *(const float4*)(W2 + r * HID + k);
            }
            #pragma unroll
            for (int ph = 0; ph < 2; ph++) {
                F4U xv[3];
                #pragma unroll
                for (int pp = 0; pp < 3; pp++)
                    xv[pp].f = *(const float4*)(hs + (ph * 3 + pp) * HID + k);
                #pragma unroll
                for (int it = 0; it < 4; it++)
                    #pragma unroll
                    for (int pp = 0; pp < 3; pp++) {
                        ffma2(acc2[it][ph * 3 + pp], wv[it].u[0], xv[pp].u[0]);
                        ffma2(acc2[it][ph * 3 + pp], wv[it].u[1], xv[pp].u[1]);
                    }
            }
        }
        #pragma unroll
        for (int it = 0; it < 4; it++) {
            int r = warp * 16 + it * 4 + rgrp;
            #pragma unroll
            for (int p = 0; p < 6; p++) {
                float s = f2sum(acc2[it][p]);
                s += __shfl_xor_sync(0xffffffffu, s, 1);
                s += __shfl_xor_sync(0xffffffffu, s, 2);
                s += __shfl_xor_sync(0xffffffffu, s, 4);
                if (ksub == 0) es[p * ENCD + r] = s;
            }
        }
    }
    __syncthreads();

    // ---- LayerNorm: warps 0..5 handle patches 0..5 ----
    if (warp < PPB) {
        float4 v = *(const float4*)(es + warp * ENCD + lane * 4);
        float s  = v.x + v.y + v.z + v.w;
        float sq = v.x * v.x + v.y * v.y + v.z * v.z + v.w * v.w;
        #pragma unroll
        for (int off = 16; off > 0; off >>= 1) {
            s  += __shfl_xor_sync(0xffffffffu, s,  off);
            sq += __shfl_xor_sync(0xffffffffu, sq, off);
        }
        float mu   = s * (1.f / ENCD);
        float var  = sq * (1.f / ENCD) - mu * mu;
        float rstd = rsqrtf(var + LNEPS);
        float4 g4  = *(const float4*)(LG + lane * 4);
        float4 b4  = *(const float4*)(LB + lane * 4);
        float4 o;
        o.x = (v.x - mu) * rstd * g4.x + b4.x;
        o.y = (v.y - mu) * rstd * g4.y + b4.y;
        o.z = (v.z - mu) * rstd * g4.z + b4.z;
        o.w = (v.w - mu) * rstd * g4.w + b4.w;
        *(float4*)(g_e + (size_t)(t * NPAD + p0 + warp) * ENCD + lane * 4) = o;
    }

    // ---- grid barrier (all 152 blocks resident; counter self-resets) ----
    __syncthreads();
    if (tid == 0) {
        __threadfence();
        unsigned old = atomicInc(&g_bar, GRIDSZ - 1);   // wraps to 0 on last
        if (old != GRIDSZ - 1u) {
            while (*(volatile unsigned*)&g_bar != 0u) __nanosleep(64);
        }
    }
    __syncthreads();
    __threadfence();

    // ---- logits: blocks 0..63 each do one 25x25 tile (4 batches x 4x4) ----
    if (bid < 64) {
        float* e1s  = S;            // [25][132] (pitch 33 float4)
        float* e2s  = S + 3300;
        float* part = S + 6600;     // [2][625]

        int b   = bid >> 4;
        int nch = (bid >> 2) & 3;
        int mch = bid & 3;
        int n0 = nch * 25, m0 = mch * 25;

        const float4* e1g = (const float4*)(g_e + (size_t)(b * NPB + n0) * ENCD);
        const float4* e2g = (const float4*)(g_e + (size_t)(NPAD + b * NPB + m0) * ENCD);
        __syncthreads();   // ensure all warps past ln-phase smem use
        for (int i = tid; i < 800; i += 256) {
            int r = i >> 5, c = i & 31;
            ((float4*)e1s)[r * 33 + c] = e1g[r * 32 + c];
            ((float4*)e2s)[r * 33 + c] = e2g[r * 32 + c];
        }
        __syncthreads();

        float scale = expf(lsc[0]);
        int kq = tid >> 7, tt = tid & 127;    // 2 k-splits of 64 floats
        if (tt < 125) {
            int rt = tt / 5, ct = tt % 5;     // row 0..24, col-group 0..4
            unsigned long long acc2[5] = {0ull, 0ull, 0ull, 0ull, 0ull};
            int c0 = kq * 16;
            #pragma unroll 4
            for (int c = 0; c < 16; c++) {
                F4U a; a.f = ((float4*)e1s)[rt * 33 + c0 + c];
                #pragma unroll
                for (int j = 0; j < 5; j++) {
                    F4U bb; bb.f = ((float4*)e2s)[(ct * 5 + j) * 33 + c0 + c];
                    ffma2(acc2[j], a.u[0], bb.u[0]);
                    ffma2(acc2[j], a.u[1], bb.u[1]);
                }
            }
            #pragma unroll
            for (int j = 0; j < 5; j++)
                part[kq * 625 + rt * 25 + ct * 5 + j] = f2sum(acc2[j]);
        }
        __syncthreads();

        for (int o = tid; o < 625; o += 256) {
            int ni = o / 25, mi = o % 25;
            float val = scale * (part[o] + part[625 + o]);
            int n = n0 + ni, m = m0 + mi;
            out[(b * NPB + n) * NPB + m] = val;              // logits_per_img
            out[40000 + (b * NPB + m) * NPB + n] = val;      // logits_per_depth
        }
    }
}

// ---------------------------------------------------------------------------
extern "C" void kernel_launch(void* const* d_in, const int* in_sizes, int n_in,
                              void* d_out, int out_size)
{
    const float* feat_c1      = (const float*)d_in[0];
    const float* feat_c2      = (const float*)d_in[1];
    const float* img_conv_w   = (const float*)d_in[3];
    const float* img_conv_b   = (const float*)d_in[4];
    const float* img_w1       = (const float*)d_in[5];
    const float* img_w2       = (const float*)d_in[6];
    const float* img_ln_g     = (const float*)d_in[7];
    const float* img_ln_b     = (const float*)d_in[8];
    const float* depth_conv_w = (const float*)d_in[9];
    const float* depth_conv_b = (const float*)d_in[10];
    const float* depth_w1     = (const float*)d_in[11];
    const float* depth_w2     = (const float*)d_in[12];
    const float* depth_ln_g   = (const float*)d_in[13];
    const float* depth_ln_b   = (const float*)d_in[14];
    const float* logit_scale  = (const float*)d_in[15];
    float* out = (float*)d_out;

    conv_kernel<<<800, 256>>>(feat_c1, feat_c2, img_conv_w, img_conv_b,
                              depth_conv_w, depth_conv_b);
    mlp_logits_kernel<<<GRIDSZ, 256>>>(img_w1, img_w2, img_ln_g, img_ln_b,
                                       depth_w1, depth_w2, depth_ln_g, depth_ln_b,
                                       logit_scale, out);
}

// round 16
// speedup vs baseline: 1.4311x; 1.0491x over previous
#include <cuda_runtime.h>
#include <cuda_bf16.h>

// Problem constants (fixed by setup_inputs)
#define CCH 256
#define NPB 100
#define NHG 10            // grid cols (nh)
#define NP 400
#define NPAD 456          // per-branch padded patch count (152 blocks x 6)
#define KDIM 256
#define HID 256
#define ENCD 128
#define LNEPS 1e-5f
#define GRIDSZ 152
#define BPB 76            // blocks per branch
#define PPB 6             // patches per block

__device__ float g_x[2 * NPAD * KDIM];   // conv+relu out; pad region stays 0 (.bss)
__device__ float g_e[2 * NPAD * ENCD];   // layernormed embeddings
__device__ unsigned g_bar = 0;           // self-resetting grid barrier counter

// packed fp32x2 helpers (ptxas never auto-emits FFMA2)
union F4U { float4 f; unsigned long long u[2]; };

__device__ __forceinline__ void ffma2(unsigned long long& d,
                                      unsigned long long a,
                                      unsigned long long b) {
    asm("fma.rn.f32x2 %0, %1, %2, %0;" : "+l"(d) : "l"(a), "l"(b));
}
__device__ __forceinline__ float f2sum(unsigned long long v) {
    float lo, hi;
    asm("mov.b64 {%0, %1}, %2;" : "=f"(lo), "=f"(hi) : "l"(v));
    return lo + hi;
}

// ---------------------------------------------------------------------------
// Kernel 1: 1x1 conv (channel reduction) + bias + relu, patch-flattened write.
// 800 blocks x 256 threads, single wave, HBM-bound (~6.2 TB/s = ceiling).
// ---------------------------------------------------------------------------
__global__ __launch_bounds__(256) void conv_kernel(
    const float* __restrict__ f1, const float* __restrict__ f2,
    const float* __restrict__ wi, const float* __restrict__ bi,
    const float* __restrict__ wd, const float* __restrict__ bd)
{
    int tid = threadIdx.x;
    int pix = tid & 63;
    int kq  = tid >> 6;                    // 0..3, channels [kq*64, kq*64+64)
    int gid = blockIdx.x * 64 + pix;       // 0..51199
    int t  = gid / 25600;                  // branch (uniform per block)
    int r  = gid % 25600;
    int b  = r / 6400;
    int r2 = r % 6400;
    int y  = r2 / 40;
    int x4 = r2 % 40;

    const float* feat = (t == 0) ? f1 : f2;
    const float* w    = (t == 0) ? wi : wd;
    float bias        = (t == 0) ? bi[0] : bd[0];

    __shared__ float ws[CCH];
    __shared__ float4 part[256];
    if (tid < 256) ws[tid] = w[tid];
    __syncthreads();

    const float4* fp = (const float4*)feat
                     + (size_t)b * CCH * 6400 + (size_t)kq * 64 * 6400
                     + y * 40 + x4;
    float4 acc = make_float4(0.f, 0.f, 0.f, 0.f);
    #pragma unroll 4
    for (int c = 0; c < 64; c++) {
        float4 v = __ldcs(fp + c * 6400);
        float wc = ws[kq * 64 + c];
        acc.x = fmaf(wc, v.x, acc.x);
        acc.y = fmaf(wc, v.y, acc.y);
        acc.z = fmaf(wc, v.z, acc.z);
        acc.w = fmaf(wc, v.w, acc.w);
    }
    part[kq * 64 + pix] = acc;
    __syncthreads();

    if (tid < 64) {
        float4 a0 = part[tid];
        float4 a1 = part[64 + tid];
        float4 a2 = part[128 + tid];
        float4 a3 = part[192 + tid];
        float4 o;
        o.x = fmaxf(a0.x + a1.x + a2.x + a3.x + bias, 0.f);
        o.y = fmaxf(a0.y + a1.y + a2.y + a3.y + bias, 0.f);
        o.z = fmaxf(a0.z + a1.z + a2.z + a3.z + bias, 0.f);
        o.w = fmaxf(a0.w + a1.w + a2.w + a3.w + bias, 0.f);

        int gid0 = blockIdx.x * 64 + tid;
        int t0  = gid0 / 25600;
        int r0  = gid0 % 25600;
        int b0  = r0 / 6400;
        int r20 = r0 % 6400;
        int y0  = r20 / 40;
        int x40 = r20 % 40;
        int v_ = y0 >> 4, ii = y0 & 15;
        int h_ = x40 >> 2, j0 = (x40 & 3) * 4;
        int patch = b0 * NPB + v_ * NHG + h_;
        int idx = (t0 * NPAD + patch) * KDIM + ii * 16 + j0;
        *(float4*)(g_x + idx) = o;
    }
}

// ---------------------------------------------------------------------------
// Kernel 2 (fused): MLP (256 -> relu 256 -> 128) + LayerNorm, grid barrier,
// then logits.  152 blocks x 512 threads (16 warps/SM: latency hiding for
// L2-hit weight LDGs), 6 patches/block (branch-padded to 456).
// Lane layout: rgrp=lane>>3 (4 rows / LDG line-group), ksub=lane&7 (16B k).
// Grid barrier: atomicInc wrap-to-0, all-resident single wave.
// ---------------------------------------------------------------------------
__global__ __launch_bounds__(512) void mlp_logits_kernel(
    const float* __restrict__ w1i, const float* __restrict__ w2i,
    const float* __restrict__ gi,  const float* __restrict__ bi,
    const float* __restrict__ w1d, const float* __restrict__ w2d,
    const float* __restrict__ gd,  const float* __restrict__ bd,
    const float* __restrict__ lsc, float* __restrict__ out)
{
    __shared__ float S[9104];
    float* xs = S;             // [6][256]  x vectors (phase 1)
    float* hs = S + 1536;      // [6][256]  hidden
    float* es = S + 3072;      // [6][128]  embeddings

    int tid = threadIdx.x;
    int bid = blockIdx.x;
    int t   = bid / BPB;        // branch
    int pg  = bid % BPB;
    int p0  = pg * PPB;         // 0..450 (>=400 are zero-pad patches)

    const float* W1 = t ? w1d : w1i;
    const float* W2 = t ? w2d : w2i;
    const float* LG = t ? gd : gi;
    const float* LB = t ? bd : bi;

    if (tid < 384) {
        const float4* xg = (const float4*)(g_x + (size_t)(t * NPAD + p0) * KDIM);
        ((float4*)xs)[tid] = xg[tid];
    }
    __syncthreads();

    int warp = tid >> 5, lane = tid & 31;
    int rgrp = lane >> 3, ksub = lane & 7;
    int koff = ksub * 4;

    // ---- GEMM1: h = relu(W1 @ x), 256 rows = 16 warps x 16 rows, one pass ----
    {
        unsigned long long acc2[4][6];
        #pragma unroll
        for (int it = 0; it < 4; it++)
            #pragma unroll
            for (int p = 0; p < 6; p++) acc2[it][p] = 0ull;

        #pragma unroll 2
        for (int kc = 0; kc < 8; kc++) {
            int k = kc * 32 + koff;
            F4U wv[4];
            #pragma unroll
            for (int it = 0; it < 4; it++) {
                int r = warp * 16 + it * 4 + rgrp;
                wv[it].f = *(const float4*)(W1 + r * HID + k);
            }
            #pragma unroll
            for (int ph = 0; ph < 2; ph++) {
                F4U xv[3];
                #pragma unroll
                for (int pp = 0; pp < 3; pp++)
                    xv[pp].f = *(const float4*)(xs + (ph * 3 + pp) * HID + k);
                #pragma unroll
                for (int it = 0; it < 4; it++)
                    #pragma unroll
                    for (int pp = 0; pp < 3; pp++) {
                        ffma2(acc2[it][ph * 3 + pp], wv[it].u[0], xv[pp].u[0]);
                        ffma2(acc2[it][ph * 3 + pp], wv[it].u[1], xv[pp].u[1]);
                    }
            }
        }
        #pragma unroll
        for (int it = 0; it < 4; it++) {
            int r = warp * 16 + it * 4 + rgrp;
            #pragma unroll
            for (int p = 0; p < 6; p++) {
                float s = f2sum(acc2[it][p]);
                s += __shfl_xor_sync(0xffffffffu, s, 1);
                s += __shfl_xor_sync(0xffffffffu, s, 2);
                s += __shfl_xor_sync(0xffffffffu, s, 4);
                if (ksub == 0) hs[p * HID + r] = fmaxf(s, 0.f);
            }
        }
    }
    __syncthreads();

    // ---- GEMM2: e = W2 @ h, 128 rows = 16 warps x 8 rows ----
    {
        unsigned long long acc2[2][6];
        #pragma unroll
        for (int it = 0; it < 2; it++)
            #pragma unroll
            for (int p = 0; p < 6; p++) acc2[it][p] = 0ull;

        #pragma unroll 2
        for (int kc = 0; kc < 8; kc++) {
            int k = kc * 32 + koff;
            F4U wv[2];
            #pragma unroll
            for (int it = 0; it < 2; it++) {
                int r = warp * 8 + it * 4 + rgrp;
                wv[it].f = *(const float4*)(W2 + r * HID + k);
            }
            #pragma unroll
            for (int ph = 0; ph < 2; ph++) {
                F4U xv[3];
                #pragma unroll
                for (int pp = 0; pp < 3; pp++)
                    xv[pp].f = *(const float4*)(hs + (ph * 3 + pp) * HID + k);
                #pragma unroll
                for (int it = 0; it < 2; it++)
                    #pragma unroll
                    for (int pp = 0; pp < 3; pp++) {
                        ffma2(acc2[it][ph * 3 + pp], wv[it].u[0], xv[pp].u[0]);
                        ffma2(acc2[it][ph * 3 + pp], wv[it].u[1], xv[pp].u[1]);
                    }
            }
        }
        #pragma unroll
        for (int it = 0; it < 2; it++) {
            int r = warp * 8 + it * 4 + rgrp;
            #pragma unroll
            for (int p = 0; p < 6; p++) {
                float s = f2sum(acc2[it][p]);
                s += __shfl_xor_sync(0xffffffffu, s, 1);
                s += __shfl_xor_sync(0xffffffffu, s, 2);
                s += __shfl_xor_sync(0xffffffffu, s, 4);
                if (ksub == 0) es[p * ENCD + r] = s;
            }
        }
    }
    __syncthreads();

    // ---- LayerNorm: warps 0..5 handle patches 0..5 ----
    if (warp < PPB) {
        float4 v = *(const float4*)(es + warp * ENCD + lane * 4);
        float s  = v.x + v.y + v.z + v.w;
        float sq = v.x * v.x + v.y * v.y + v.z * v.z + v.w * v.w;
        #pragma unroll
        for (int off = 16; off > 0; off >>= 1) {
            s  += __shfl_xor_sync(0xffffffffu, s,  off);
            sq += __shfl_xor_sync(0xffffffffu, sq, off);
        }
        float mu   = s * (1.f / ENCD);
        float var  = sq * (1.f / ENCD) - mu * mu;
        float rstd = rsqrtf(var + LNEPS);
        float4 g4  = *(const float4*)(LG + lane * 4);
        float4 b4  = *(const float4*)(LB + lane * 4);
        float4 o;
        o.x = (v.x - mu) * rstd * g4.x + b4.x;
        o.y = (v.y - mu) * rstd * g4.y + b4.y;
        o.z = (v.z - mu) * rstd * g4.z + b4.z;
        o.w = (v.w - mu) * rstd * g4.w + b4.w;
        *(float4*)(g_e + (size_t)(t * NPAD + p0 + warp) * ENCD + lane * 4) = o;
    }

    // ---- grid barrier (all 152 blocks resident; counter self-resets) ----
    __threadfence();     // release g_e writes (all threads)
    __syncthreads();
    if (tid == 0) {
        unsigned old = atomicInc(&g_bar, GRIDSZ - 1);   // wraps to 0 on last
        if (old != GRIDSZ - 1u) {
            while (*(volatile unsigned*)&g_bar != 0u) __nanosleep(64);
        }
    }
    __syncthreads();
    __threadfence();

    // ---- logits: blocks 0..63 each do one 25x25 tile (4 batches x 4x4) ----
    if (bid < 64) {
        float* e1s  = S;            // [25][132] (pitch 33 float4)
        float* e2s  = S + 3300;
        float* part = S + 6600;     // [4][625]

        int b   = bid >> 4;
        int nch = (bid >> 2) & 3;
        int mch = bid & 3;
        int n0 = nch * 25, m0 = mch * 25;

        const float4* e1g = (const float4*)(g_e + (size_t)(b * NPB + n0) * ENCD);
        const float4* e2g = (const float4*)(g_e + (size_t)(NPAD + b * NPB + m0) * ENCD);
        __syncthreads();   // all warps done with mlp-phase smem
        for (int i = tid; i < 800; i += 512) {
            int r = i >> 5, c = i & 31;
            ((float4*)e1s)[r * 33 + c] = e1g[r * 32 + c];
            ((float4*)e2s)[r * 33 + c] = e2g[r * 32 + c];
        }
        __syncthreads();

        float scale = expf(lsc[0]);
        int kq = tid >> 7, tt = tid & 127;    // 4 k-splits of 32 floats
        if (tt < 125) {
            int rt = tt / 5, ct = tt % 5;     // row 0..24, col-group 0..4
            unsigned long long acc2[5] = {0ull, 0ull, 0ull, 0ull, 0ull};
            int c0 = kq * 8;
            #pragma unroll
            for (int c = 0; c < 8; c++) {
                F4U a; a.f = ((float4*)e1s)[rt * 33 + c0 + c];
                #pragma unroll
                for (int j = 0; j < 5; j++) {
                    F4U bb; bb.f = ((float4*)e2s)[(ct * 5 + j) * 33 + c0 + c];
                    ffma2(acc2[j], a.u[0], bb.u[0]);
                    ffma2(acc2[j], a.u[1], bb.u[1]);
                }
            }
            #pragma unroll
            for (int j = 0; j < 5; j++)
                part[kq * 625 + rt * 25 + ct * 5 + j] = f2sum(acc2[j]);
        }
        __syncthreads();

        for (int o = tid; o < 625; o += 512) {
            int ni = o / 25, mi = o % 25;
            float val = scale * (part[o] + part[625 + o] + part[1250 + o] + part[1875 + o]);
            int n = n0 + ni, m = m0 + mi;
            out[(b * NPB + n) * NPB + m] = val;              // logits_per_img
            out[40000 + (b * NPB + m) * NPB + n] = val;      // logits_per_depth
        }
    }
}

// ---------------------------------------------------------------------------
extern "C" void kernel_launch(void* const* d_in, const int* in_sizes, int n_in,
                              void* d_out, int out_size)
{
    const float* feat_c1      = (const float*)d_in[0];
    const float* feat_c2      = (const float*)d_in[1];
    const float* img_conv_w   = (const float*)d_in[3];
    const float* img_conv_b   = (const float*)d_in[4];
    const float* img_w1       = (const float*)d_in[5];
    const float* img_w2       = (const float*)d_in[6];
    const float* img_ln_g     = (const float*)d_in[7];
    const float* img_ln_b     = (const float*)d_in[8];
    const float* depth_conv_w = (const float*)d_in[9];
    const float* depth_conv_b = (const float*)d_in[10];
    const float* depth_w1     = (const float*)d_in[11];
    const float* depth_w2     = (const float*)d_in[12];
    const float* depth_ln_g   = (const float*)d_in[13];
    const float* depth_ln_b   = (const float*)d_in[14];
    const float* logit_scale  = (const float*)d_in[15];
    float* out = (float*)d_out;

    conv_kernel<<<800, 256>>>(feat_c1, feat_c2, img_conv_w, img_conv_b,
                              depth_conv_w, depth_conv_b);
    mlp_logits_kernel<<<GRIDSZ, 512>>>(img_w1, img_w2, img_ln_g, img_ln_b,
                                       depth_w1, depth_w2, depth_ln_g, depth_ln_b,
                                       logit_scale, out);
}